// round 12
// baseline (speedup 1.0000x reference)
#include <cuda_runtime.h>
#include <cuda_bf16.h>
#include <cstdint>

// Problem constants
#define BB   4
#define NN   10000
#define EE   160000
#define BN   40000
#define CAP  96

// ---------------- device scratch ----------------
__device__ float  g_h[BN * 128];
__device__ float  g_scat[BN * 128];
__device__ float  g_asrc[NN * 4];      // [n][b], accumulated via atomics
__device__ float  g_atgt[NN * 4];
__device__ float4 g_w4[EE];
__device__ float  g_expsum[1];
__device__ int    g_cursor[NN];
__device__ unsigned int g_csr[NN * CAP];   // packed (e<<14)|tgt (e is 18 bits)
// Precomputed bf16 hi/lo weight images in smem-pitched layout
__device__ uint4 g_TBH[2176], g_TBL[2176];     // Wt^T  [n=128][k=128], pitch 136
__device__ uint4 g_OBH[4224], g_OBL[4224];     // Wc^T  [n=128][k=256], pitch 264

// ---------------- helpers ----------------
__device__ __forceinline__ void mma16816(float* d, const uint32_t* a,
                                         const uint32_t* b) {
    asm volatile(
        "mma.sync.aligned.m16n8k16.row.col.f32.bf16.bf16.f32 "
        "{%0,%1,%2,%3}, {%4,%5,%6,%7}, {%8,%9}, {%0,%1,%2,%3};"
        : "+f"(d[0]), "+f"(d[1]), "+f"(d[2]), "+f"(d[3])
        : "r"(a[0]), "r"(a[1]), "r"(a[2]), "r"(a[3]), "r"(b[0]), "r"(b[1]));
}
__device__ __forceinline__ void split_bf16(float v, uint16_t& h, uint16_t& l) {
    __nv_bfloat16 hb = __float2bfloat16(v);
    __nv_bfloat16 lb = __float2bfloat16(v - __bfloat162float(hb));
    h = *(uint16_t*)&hb;
    l = *(uint16_t*)&lb;
}
__device__ __forceinline__ void split_pack2(float x, float y, uint32_t& hi,
                                            uint32_t& lo) {
    uint16_t hx, lx, hy, ly;
    split_bf16(x, hx, lx);
    split_bf16(y, hy, ly);
    hi = (uint32_t)hx | ((uint32_t)hy << 16);
    lo = (uint32_t)lx | ((uint32_t)ly << 16);
}
// exp(x) on [-1,1], degree-7 Taylor; keeps MUFU free
__device__ __forceinline__ float exp_poly(float x) {
    float p = 1.98412698e-4f;
    p = fmaf(p, x, 1.38888889e-3f);
    p = fmaf(p, x, 8.33333333e-3f);
    p = fmaf(p, x, 4.16666667e-2f);
    p = fmaf(p, x, 1.66666667e-1f);
    p = fmaf(p, x, 0.5f);
    p = fmaf(p, x, 1.0f);
    p = fmaf(p, x, 1.0f);
    return p;
}

#define TPB 136         // transform B pitch (bf16 elems)
#define OPB 264         // out B pitch (bf16 elems)

// ---------------- K0: zero ----------------
__global__ void zero_kernel() {
    int i = blockIdx.x * blockDim.x + threadIdx.x;
    if (i == 0) g_expsum[0] = 0.0f;
    if (i < NN) g_cursor[i] = 0;
    if (i < NN * 4) { g_asrc[i] = 0.0f; g_atgt[i] = 0.0f; }
}

// ---------------- prep: weight bf16 hi/lo images (runs once per launch) -----
__global__ void prep_kernel(const float* __restrict__ Wt,
                            const float* __restrict__ Wc) {
    int idx = blockIdx.x * blockDim.x + threadIdx.x;
    if (idx < 16384) {
        int k = idx >> 7, n = idx & 127;        // Wt[k][n]
        uint16_t h, l;
        split_bf16(Wt[idx], h, l);
        ((uint16_t*)g_TBH)[n * TPB + k] = h;
        ((uint16_t*)g_TBL)[n * TPB + k] = l;
    } else if (idx < 49152) {
        int t = idx - 16384;
        int k = t >> 7, n = t & 127;            // Wc[k][n]
        uint16_t h, l;
        split_bf16(Wc[t], h, l);
        ((uint16_t*)g_OBH)[n * OPB + k] = h;
        ((uint16_t*)g_OBL)[n * OPB + k] = l;
    }
}

// ---------------- K1: fill bucketed CSR (edges int32) ----------------
__global__ void fill_kernel(const int* __restrict__ edges) {
    int e = blockIdx.x * blockDim.x + threadIdx.x;
    if (e < EE) {
        int2 st = *(const int2*)(edges + 2 * e);
        int p = atomicAdd(&g_cursor[st.x], 1);
        if (p < CAP)
            g_csr[st.x * CAP + p] = ((unsigned int)e << 14) | (unsigned int)st.y;
    }
}

// ======================= transform (tensor core) =======================
// block: 256 thr = 8 warps = 4 M-groups(16 nodes) x 2 N-halves(64 cols).
#define TPA 68          // A row pitch in u32 words (136 bf16 elems)
#define T_BH   0
#define T_BL   34816
#define T_AH   69632
#define T_AL   87040
#define T_BIAS 104448
#define T_WAS  104960
#define T_WAT  105472
#define T_SMEM 105984

__global__ void __launch_bounds__(256) transform_mma(
    const float* __restrict__ nf, const float* __restrict__ bt,
    const float* __restrict__ Wa) {
    extern __shared__ char sm[];
    uint16_t* BH = (uint16_t*)(sm + T_BH);
    uint16_t* BL = (uint16_t*)(sm + T_BL);
    uint32_t* AH = (uint32_t*)(sm + T_AH);
    uint32_t* AL = (uint32_t*)(sm + T_AL);
    float* bias = (float*)(sm + T_BIAS);
    float* waS  = (float*)(sm + T_WAS);
    float* waT  = (float*)(sm + T_WAT);

    const int tid = threadIdx.x, lane = tid & 31, w = tid >> 5;
    const int nb = blockIdx.x * 64;

    // stage B: straight uint4 copy of precomputed images
    {
        uint4* dH = (uint4*)BH;
        uint4* dL = (uint4*)BL;
        for (int i = tid; i < 2176; i += 256) { dH[i] = g_TBH[i]; dL[i] = g_TBL[i]; }
    }
    // stage A: 64 node rows, bf16 hi/lo packed pairs
    for (int i = tid; i < 2048; i += 256) {
        int node = i >> 5, c4 = i & 31;
        float4 v = *(const float4*)(nf + (size_t)(nb + node) * 128 + c4 * 4);
        uint32_t h01, l01, h23, l23;
        split_pack2(v.x, v.y, h01, l01);
        split_pack2(v.z, v.w, h23, l23);
        int widx = node * TPA + c4 * 2;
        AH[widx] = h01; AH[widx + 1] = h23;
        AL[widx] = l01; AL[widx + 1] = l23;
    }
    if (tid < 128) { bias[tid] = bt[tid]; waS[tid] = Wa[tid]; waT[tid] = Wa[128 + tid]; }
    __syncthreads();

    const int g = lane >> 2, t = lane & 3;
    const int mg = w >> 1, nh = w & 1;
    const int nbase = nh * 64;

    float D[8][4];
#pragma unroll
    for (int nt = 0; nt < 8; nt++)
#pragma unroll
        for (int j = 0; j < 4; j++) D[nt][j] = 0.0f;

    const uint32_t arow0 = (mg * 16 + g) * TPA;
    const uint32_t arow1 = arow0 + 8 * TPA;

#pragma unroll
    for (int ks = 0; ks < 8; ks++) {
        const int kw = ks * 8 + t;
        uint32_t ah[4], al[4];
        ah[0] = AH[arow0 + kw];     ah[1] = AH[arow1 + kw];
        ah[2] = AH[arow0 + kw + 4]; ah[3] = AH[arow1 + kw + 4];
        al[0] = AL[arow0 + kw];     al[1] = AL[arow1 + kw];
        al[2] = AL[arow0 + kw + 4]; al[3] = AL[arow1 + kw + 4];
#pragma unroll
        for (int nt = 0; nt < 8; nt++) {
            int n = nbase + nt * 8 + g;
            const uint32_t* bhp = (const uint32_t*)(BH + n * TPB);
            const uint32_t* blp = (const uint32_t*)(BL + n * TPB);
            uint32_t bh[2], bl[2];
            bh[0] = bhp[kw]; bh[1] = bhp[kw + 4];
            bl[0] = blp[kw]; bl[1] = blp[kw + 4];
            mma16816(D[nt], ah, bh);
            mma16816(D[nt], ah, bl);
            mma16816(D[nt], al, bh);
        }
    }

    // epilogue: relu + bias, store h, partial attention dots
    const int node0 = nb + mg * 16 + g;
    const int node1 = node0 + 8;
    float pS0 = 0.f, pS1 = 0.f, pT0 = 0.f, pT1 = 0.f;
#pragma unroll
    for (int nt = 0; nt < 8; nt++) {
        int c = nbase + nt * 8 + 2 * t;
        float b0 = bias[c], b1 = bias[c + 1];
        float h00 = fmaxf(D[nt][0] + b0, 0.f), h01 = fmaxf(D[nt][1] + b1, 0.f);
        float h10 = fmaxf(D[nt][2] + b0, 0.f), h11 = fmaxf(D[nt][3] + b1, 0.f);
        *(float2*)(g_h + (size_t)node0 * 128 + c) = make_float2(h00, h01);
        *(float2*)(g_h + (size_t)node1 * 128 + c) = make_float2(h10, h11);
        float s0 = waS[c], s1 = waS[c + 1], t0 = waT[c], t1 = waT[c + 1];
        pS0 += h00 * s0 + h01 * s1;  pS1 += h10 * s0 + h11 * s1;
        pT0 += h00 * t0 + h01 * t1;  pT1 += h10 * t0 + h11 * t1;
    }
    pS0 += __shfl_xor_sync(0xFFFFFFFFu, pS0, 1); pS0 += __shfl_xor_sync(0xFFFFFFFFu, pS0, 2);
    pS1 += __shfl_xor_sync(0xFFFFFFFFu, pS1, 1); pS1 += __shfl_xor_sync(0xFFFFFFFFu, pS1, 2);
    pT0 += __shfl_xor_sync(0xFFFFFFFFu, pT0, 1); pT0 += __shfl_xor_sync(0xFFFFFFFFu, pT0, 2);
    pT1 += __shfl_xor_sync(0xFFFFFFFFu, pT1, 1); pT1 += __shfl_xor_sync(0xFFFFFFFFu, pT1, 2);
    if (t == 0) {
        int b0i = node0 / NN, n0 = node0 - b0i * NN;
        atomicAdd(&g_asrc[n0 * 4 + b0i], pS0);
        atomicAdd(&g_atgt[n0 * 4 + b0i], pT0);
        int b1i = node1 / NN, n1 = node1 - b1i * NN;
        atomicAdd(&g_asrc[n1 * 4 + b1i], pS1);
        atomicAdd(&g_atgt[n1 * 4 + b1i], pT1);
    }
}

// ---------------- K3: edge weights, 2 edges/thread ----------------
__global__ void __launch_bounds__(256) edgew_kernel(
    const int* __restrict__ edges, const float* __restrict__ ba) {
    int base = (blockIdx.x * blockDim.x + threadIdx.x) * 2;
    float partial = 0.0f;
    float ba0 = ba[0];
    if (base < EE) {
        int4 e4 = *(const int4*)(edges + 2 * base);
        float4 as0 = *(const float4*)(g_asrc + e4.x * 4);
        float4 at0 = *(const float4*)(g_atgt + e4.y * 4);
        float4 as1 = *(const float4*)(g_asrc + e4.z * 4);
        float4 at1 = *(const float4*)(g_atgt + e4.w * 4);
        float z0[4] = {as0.x + at0.x, as0.y + at0.y, as0.z + at0.z, as0.w + at0.w};
        float z1[4] = {as1.x + at1.x, as1.y + at1.y, as1.z + at1.z, as1.w + at1.w};
        float4 w0, w1;
        float* wp0 = (float*)&w0;
        float* wp1 = (float*)&w1;
#pragma unroll
        for (int b = 0; b < 4; b++) {
            float a0 = 1.0f - __fdividef(2.0f, __expf(2.0f * (z0[b] + ba0)) + 1.0f);
            float a1 = 1.0f - __fdividef(2.0f, __expf(2.0f * (z1[b] + ba0)) + 1.0f);
            float e0 = exp_poly(a0), e1 = exp_poly(a1);
            wp0[b] = e0; wp1[b] = e1;
            partial += e0 + e1;
        }
        g_w4[base] = w0;
        g_w4[base + 1] = w1;
    }
#pragma unroll
    for (int o = 16; o > 0; o >>= 1)
        partial += __shfl_xor_sync(0xFFFFFFFFu, partial, o);
    if ((threadIdx.x & 31) == 0) atomicAdd(g_expsum, partial);
}

// ---------------- K4: aggregate. One warp per node, all 4 batches ----------
__global__ void __launch_bounds__(256) agg_kernel() {
    int n = blockIdx.x * 8 + (threadIdx.x >> 5);
    int lane = threadIdx.x & 31;
    if (n >= NN) return;
    int cnt = g_cursor[n];
    if (cnt > CAP) cnt = CAP;
    float invS = 1.0f / g_expsum[0];
    const float4* hb = (const float4*)g_h;
    const unsigned int* bucket = g_csr + n * CAP;
    float4 a0 = make_float4(0.f, 0.f, 0.f, 0.f), a1 = a0, a2 = a0, a3 = a0;
    for (int j = 0; j < cnt; j++) {
        unsigned int v = bucket[j];
        int e = (int)(v >> 14);
        int tgt = (int)(v & 0x3FFFu);
        float4 w = g_w4[e];
        float4 h0 = hb[(size_t)(0 * NN + tgt) * 32 + lane];
        float4 h1 = hb[(size_t)(1 * NN + tgt) * 32 + lane];
        float4 h2 = hb[(size_t)(2 * NN + tgt) * 32 + lane];
        float4 h3 = hb[(size_t)(3 * NN + tgt) * 32 + lane];
        a0.x += w.x * h0.x; a0.y += w.x * h0.y; a0.z += w.x * h0.z; a0.w += w.x * h0.w;
        a1.x += w.y * h1.x; a1.y += w.y * h1.y; a1.z += w.y * h1.z; a1.w += w.y * h1.w;
        a2.x += w.z * h2.x; a2.y += w.z * h2.y; a2.z += w.z * h2.z; a2.w += w.z * h2.w;
        a3.x += w.w * h3.x; a3.y += w.w * h3.y; a3.z += w.w * h3.z; a3.w += w.w * h3.w;
    }
    a0.x *= invS; a0.y *= invS; a0.z *= invS; a0.w *= invS;
    a1.x *= invS; a1.y *= invS; a1.z *= invS; a1.w *= invS;
    a2.x *= invS; a2.y *= invS; a2.z *= invS; a2.w *= invS;
    a3.x *= invS; a3.y *= invS; a3.z *= invS; a3.w *= invS;
    float4* sc = (float4*)g_scat;
    sc[(size_t)(0 * NN + n) * 32 + lane] = a0;
    sc[(size_t)(1 * NN + n) * 32 + lane] = a1;
    sc[(size_t)(2 * NN + n) * 32 + lane] = a2;
    sc[(size_t)(3 * NN + n) * 32 + lane] = a3;
}

// ======================= output GEMM (tensor core) =======================
#define OPA 132         // A row pitch in u32 words (264 bf16 elems)
#define O_BH   0
#define O_BL   67584
#define O_AH   135168
#define O_AL   168960
#define O_BIAS 202752
#define O_SMEM 203264

__global__ void __launch_bounds__(256) out_mma(
    const float* __restrict__ bc, float* __restrict__ out) {
    extern __shared__ char sm[];
    uint16_t* BH = (uint16_t*)(sm + O_BH);
    uint16_t* BL = (uint16_t*)(sm + O_BL);
    uint32_t* AH = (uint32_t*)(sm + O_AH);
    uint32_t* AL = (uint32_t*)(sm + O_AL);
    float* bias = (float*)(sm + O_BIAS);

    const int tid = threadIdx.x, lane = tid & 31, w = tid >> 5;
    const int nb = blockIdx.x * 64;

    // stage B: straight uint4 copy of precomputed images
    {
        uint4* dH = (uint4*)BH;
        uint4* dL = (uint4*)BL;
        for (int i = tid; i < 4224; i += 256) { dH[i] = g_OBH[i]; dL[i] = g_OBL[i]; }
    }
    // stage A: 64 rows of [h(128) | scat(128)]
    for (int i = tid; i < 4096; i += 256) {
        int node = i >> 6, c4 = i & 63;
        float4 v;
        if (c4 < 32)
            v = *(const float4*)(g_h + (size_t)(nb + node) * 128 + c4 * 4);
        else
            v = *(const float4*)(g_scat + (size_t)(nb + node) * 128 + (c4 - 32) * 4);
        uint32_t h01, l01, h23, l23;
        split_pack2(v.x, v.y, h01, l01);
        split_pack2(v.z, v.w, h23, l23);
        int widx = node * OPA + c4 * 2;
        AH[widx] = h01; AH[widx + 1] = h23;
        AL[widx] = l01; AL[widx + 1] = l23;
    }
    if (tid < 128) bias[tid] = bc[tid];
    __syncthreads();

    const int g = lane >> 2, t = lane & 3;
    const int mg = w >> 1, nh = w & 1;
    const int nbase = nh * 64;

    float D[8][4];
#pragma unroll
    for (int nt = 0; nt < 8; nt++)
#pragma unroll
        for (int j = 0; j < 4; j++) D[nt][j] = 0.0f;

    const uint32_t arow0 = (mg * 16 + g) * OPA;
    const uint32_t arow1 = arow0 + 8 * OPA;

#pragma unroll
    for (int ks = 0; ks < 16; ks++) {
        const int kw = ks * 8 + t;
        uint32_t ah[4], al[4];
        ah[0] = AH[arow0 + kw];     ah[1] = AH[arow1 + kw];
        ah[2] = AH[arow0 + kw + 4]; ah[3] = AH[arow1 + kw + 4];
        al[0] = AL[arow0 + kw];     al[1] = AL[arow1 + kw];
        al[2] = AL[arow0 + kw + 4]; al[3] = AL[arow1 + kw + 4];
#pragma unroll
        for (int nt = 0; nt < 8; nt++) {
            int n = nbase + nt * 8 + g;
            const uint32_t* bhp = (const uint32_t*)(BH + n * OPB);
            const uint32_t* blp = (const uint32_t*)(BL + n * OPB);
            uint32_t bh[2], bl[2];
            bh[0] = bhp[kw]; bh[1] = bhp[kw + 4];
            bl[0] = blp[kw]; bl[1] = blp[kw + 4];
            mma16816(D[nt], ah, bh);
            mma16816(D[nt], ah, bl);
            mma16816(D[nt], al, bh);
        }
    }

    const int node0 = nb + mg * 16 + g;
    const int node1 = node0 + 8;
#pragma unroll
    for (int nt = 0; nt < 8; nt++) {
        int c = nbase + nt * 8 + 2 * t;
        float b0 = bias[c], b1 = bias[c + 1];
        float h00 = fmaxf(D[nt][0] + b0, 0.f), h01 = fmaxf(D[nt][1] + b1, 0.f);
        float h10 = fmaxf(D[nt][2] + b0, 0.f), h11 = fmaxf(D[nt][3] + b1, 0.f);
        *(float2*)(out + (size_t)node0 * 128 + c) = make_float2(h00, h01);
        *(float2*)(out + (size_t)node1 * 128 + c) = make_float2(h10, h11);
    }
}

// ---------------- launch ----------------
extern "C" void kernel_launch(void* const* d_in, const int* in_sizes, int n_in,
                              void* d_out, int out_size) {
    const float* nf    = (const float*)d_in[0];
    const int*   edges = (const int*)d_in[1];   // int32 (jax x64 disabled)
    const float* Wt    = (const float*)d_in[2];
    const float* bt    = (const float*)d_in[3];
    const float* Wa    = (const float*)d_in[4];
    const float* ba    = (const float*)d_in[5];
    const float* Wc    = (const float*)d_in[6];
    const float* bc    = (const float*)d_in[7];
    float*       out   = (float*)d_out;

    cudaFuncSetAttribute(transform_mma,
                         cudaFuncAttributeMaxDynamicSharedMemorySize, T_SMEM);
    cudaFuncSetAttribute(out_mma,
                         cudaFuncAttributeMaxDynamicSharedMemorySize, O_SMEM);

    zero_kernel<<<(NN * 4 + 255) / 256, 256>>>();
    prep_kernel<<<192, 256>>>(Wt, Wc);
    fill_kernel<<<(EE + 255) / 256, 256>>>(edges);
    transform_mma<<<BN / 64, 256, T_SMEM>>>(nf, bt, Wa);
    edgew_kernel<<<(EE / 2 + 255) / 256, 256>>>(edges, ba);
    agg_kernel<<<(NN + 7) / 8, 256>>>();
    out_mma<<<BN / 64, 256, O_SMEM>>>(bc, out);
}

// round 13
// speedup vs baseline: 1.8248x; 1.8248x over previous
#include <cuda_runtime.h>
#include <cuda_bf16.h>
#include <cstdint>

// Problem constants
#define BB   4
#define NN   10000
#define EE   160000
#define BN   40000
#define CAP  96

// ---------------- device scratch ----------------
__device__ float  g_h[BN * 128];
__device__ float  g_scat[BN * 128];
__device__ float  g_asrc[NN * 4];
__device__ float  g_atgt[NN * 4];
__device__ float4 g_w4[EE];
__device__ float  g_expsum[1];
__device__ int    g_cursor[NN];
__device__ unsigned int g_csr[NN * CAP];
// Precomputed bf16 hi/lo weight images, pitched [n=128][k=128], pitch 136 elems
__device__ uint4 g_TBH[2176], g_TBL[2176];        // Wt^T
__device__ uint4 g_OBH[2][2176], g_OBL[2][2176];  // Wc^T, two K=128 chunks

#define TPA 68          // A row pitch in u32 words (136 bf16)
#define TPB 136         // B row pitch in bf16 elems

// ---------------- helpers ----------------
__device__ __forceinline__ uint32_t smem_u32(const void* p) {
    uint32_t a;
    asm("{ .reg .u64 t; cvta.to.shared.u64 t, %1; cvt.u32.u64 %0, t; }"
        : "=r"(a) : "l"(p));
    return a;
}
__device__ __forceinline__ void mma16816(float* d, const uint32_t* a,
                                         const uint32_t* b) {
    asm volatile(
        "mma.sync.aligned.m16n8k16.row.col.f32.bf16.bf16.f32 "
        "{%0,%1,%2,%3}, {%4,%5,%6,%7}, {%8,%9}, {%0,%1,%2,%3};"
        : "+f"(d[0]), "+f"(d[1]), "+f"(d[2]), "+f"(d[3])
        : "r"(a[0]), "r"(a[1]), "r"(a[2]), "r"(a[3]), "r"(b[0]), "r"(b[1]));
}
__device__ __forceinline__ void ldsm_x4(uint32_t addr, uint32_t* r) {
    asm volatile(
        "ldmatrix.sync.aligned.m8n8.x4.shared.b16 {%0,%1,%2,%3}, [%4];"
        : "=r"(r[0]), "=r"(r[1]), "=r"(r[2]), "=r"(r[3]) : "r"(addr));
}
__device__ __forceinline__ void split_bf16(float v, uint16_t& h, uint16_t& l) {
    __nv_bfloat16 hb = __float2bfloat16(v);
    __nv_bfloat16 lb = __float2bfloat16(v - __bfloat162float(hb));
    h = *(uint16_t*)&hb;
    l = *(uint16_t*)&lb;
}
__device__ __forceinline__ void split_pack2(float x, float y, uint32_t& hi,
                                            uint32_t& lo) {
    uint16_t hx, lx, hy, ly;
    split_bf16(x, hx, lx);
    split_bf16(y, hy, ly);
    hi = (uint32_t)hx | ((uint32_t)hy << 16);
    lo = (uint32_t)lx | ((uint32_t)ly << 16);
}
__device__ __forceinline__ float exp_poly(float x) {
    float p = 1.98412698e-4f;
    p = fmaf(p, x, 1.38888889e-3f);
    p = fmaf(p, x, 8.33333333e-3f);
    p = fmaf(p, x, 4.16666667e-2f);
    p = fmaf(p, x, 1.66666667e-1f);
    p = fmaf(p, x, 0.5f);
    p = fmaf(p, x, 1.0f);
    p = fmaf(p, x, 1.0f);
    return p;
}

// K=128 bf16-split MMA mainloop via ldmatrix.x4. Warp: 16 rows x 64 cols.
__device__ __forceinline__ void mma_mainloop(
    uint32_t aH, uint32_t aL, uint32_t bH, uint32_t bL,
    int lane, int mg, int nbase, float D[8][4]) {
    const int m = lane >> 3, r8 = lane & 7;
    // A: M0=rows0-7/k0, M1=rows8-15/k0, M2=rows0-7/+16B, M3=rows8-15/+16B
    uint32_t aoff = (uint32_t)((mg * 16 + r8 + ((m & 1) << 3)) * (TPA * 4) +
                               ((m >> 1) << 4));
    uint32_t aHa = aH + aoff, aLa = aL + aoff;
    // B: M0=n0-7/k0, M1=n0-7/+16B, M2=n8-15/k0, M3=n8-15/+16B
    uint32_t bHa[4], bLa[4];
#pragma unroll
    for (int p = 0; p < 4; p++) {
        uint32_t boff = (uint32_t)((nbase + p * 16 + r8 + ((m >> 1) << 3)) *
                                   (TPB * 2) + ((m & 1) << 4));
        bHa[p] = bH + boff;
        bLa[p] = bL + boff;
    }
#pragma unroll
    for (int ks = 0; ks < 8; ks++) {
        uint32_t ah[4], al[4];
        ldsm_x4(aHa + ks * 32, ah);
        ldsm_x4(aLa + ks * 32, al);
        uint32_t bh[4][4], bl[4][4];
#pragma unroll
        for (int p = 0; p < 4; p++) {
            ldsm_x4(bHa[p] + ks * 32, bh[p]);
            ldsm_x4(bLa[p] + ks * 32, bl[p]);
        }
#pragma unroll
        for (int p = 0; p < 4; p++) {
            mma16816(D[2 * p],     ah, &bh[p][0]);
            mma16816(D[2 * p],     ah, &bl[p][0]);
            mma16816(D[2 * p],     al, &bh[p][0]);
            mma16816(D[2 * p + 1], ah, &bh[p][2]);
            mma16816(D[2 * p + 1], ah, &bl[p][2]);
            mma16816(D[2 * p + 1], al, &bh[p][2]);
        }
    }
}

// stage 64 node rows (128 floats each) as bf16 hi/lo into pitched A buffers
__device__ __forceinline__ void stage_A64(const float* __restrict__ src, int nb,
                                          uint32_t* AH, uint32_t* AL, int tid) {
    for (int i = tid; i < 2048; i += 256) {
        int node = i >> 5, c4 = i & 31;
        float4 v = *(const float4*)(src + (size_t)(nb + node) * 128 + c4 * 4);
        uint32_t h01, l01, h23, l23;
        split_pack2(v.x, v.y, h01, l01);
        split_pack2(v.z, v.w, h23, l23);
        int widx = node * TPA + c4 * 2;
        AH[widx] = h01; AH[widx + 1] = h23;
        AL[widx] = l01; AL[widx + 1] = l23;
    }
}

// ---------------- K0: zero ----------------
__global__ void zero_kernel() {
    int i = blockIdx.x * blockDim.x + threadIdx.x;
    if (i == 0) g_expsum[0] = 0.0f;
    if (i < NN) g_cursor[i] = 0;
    if (i < NN * 4) { g_asrc[i] = 0.0f; g_atgt[i] = 0.0f; }
}

// ---------------- prep: weight bf16 hi/lo images ----------------
__global__ void prep_kernel(const float* __restrict__ Wt,
                            const float* __restrict__ Wc) {
    int idx = blockIdx.x * blockDim.x + threadIdx.x;
    if (idx < 16384) {
        int k = idx >> 7, n = idx & 127;
        uint16_t h, l;
        split_bf16(Wt[idx], h, l);
        ((uint16_t*)g_TBH)[n * TPB + k] = h;
        ((uint16_t*)g_TBL)[n * TPB + k] = l;
    } else if (idx < 49152) {
        int t = idx - 16384;
        int k = t >> 7, n = t & 127;
        int c = k >> 7, kk = k & 127;
        uint16_t h, l;
        split_bf16(Wc[t], h, l);
        ((uint16_t*)g_OBH[c])[n * TPB + kk] = h;
        ((uint16_t*)g_OBL[c])[n * TPB + kk] = l;
    }
}

// ---------------- K1: fill bucketed CSR ----------------
__global__ void fill_kernel(const int* __restrict__ edges) {
    int e = blockIdx.x * blockDim.x + threadIdx.x;
    if (e < EE) {
        int2 st = *(const int2*)(edges + 2 * e);
        int p = atomicAdd(&g_cursor[st.x], 1);
        if (p < CAP)
            g_csr[st.x * CAP + p] = ((unsigned int)e << 14) | (unsigned int)st.y;
    }
}

// ======================= transform GEMM =======================
#define T_BH   0
#define T_BL   34816
#define T_AH   69632
#define T_AL   87040
#define T_BIAS 104448
#define T_WAS  104960
#define T_WAT  105472
#define T_SMEM 105984

__global__ void __launch_bounds__(256, 2) transform_mma(
    const float* __restrict__ nf, const float* __restrict__ bt,
    const float* __restrict__ Wa) {
    extern __shared__ char sm[];
    uint32_t sb = smem_u32(sm);
    float* bias = (float*)(sm + T_BIAS);
    float* waS  = (float*)(sm + T_WAS);
    float* waT  = (float*)(sm + T_WAT);

    const int tid = threadIdx.x, lane = tid & 31, w = tid >> 5;
    const int nb = blockIdx.x * 64;

    {
        uint4* dH = (uint4*)(sm + T_BH);
        uint4* dL = (uint4*)(sm + T_BL);
        for (int i = tid; i < 2176; i += 256) { dH[i] = g_TBH[i]; dL[i] = g_TBL[i]; }
    }
    stage_A64(nf, nb, (uint32_t*)(sm + T_AH), (uint32_t*)(sm + T_AL), tid);
    if (tid < 128) { bias[tid] = bt[tid]; waS[tid] = Wa[tid]; waT[tid] = Wa[128 + tid]; }
    __syncthreads();

    const int mg = w >> 1, nh = w & 1;
    const int nbase = nh * 64;

    float D[8][4];
#pragma unroll
    for (int nt = 0; nt < 8; nt++)
#pragma unroll
        for (int j = 0; j < 4; j++) D[nt][j] = 0.0f;

    mma_mainloop(sb + T_AH, sb + T_AL, sb + T_BH, sb + T_BL, lane, mg, nbase, D);

    // epilogue
    const int g = lane >> 2, t = lane & 3;
    const int node0 = nb + mg * 16 + g;
    const int node1 = node0 + 8;
    float pS0 = 0.f, pS1 = 0.f, pT0 = 0.f, pT1 = 0.f;
#pragma unroll
    for (int nt = 0; nt < 8; nt++) {
        int c = nbase + nt * 8 + 2 * t;
        float b0 = bias[c], b1 = bias[c + 1];
        float h00 = fmaxf(D[nt][0] + b0, 0.f), h01 = fmaxf(D[nt][1] + b1, 0.f);
        float h10 = fmaxf(D[nt][2] + b0, 0.f), h11 = fmaxf(D[nt][3] + b1, 0.f);
        *(float2*)(g_h + (size_t)node0 * 128 + c) = make_float2(h00, h01);
        *(float2*)(g_h + (size_t)node1 * 128 + c) = make_float2(h10, h11);
        float s0 = waS[c], s1 = waS[c + 1], t0 = waT[c], t1 = waT[c + 1];
        pS0 += h00 * s0 + h01 * s1;  pS1 += h10 * s0 + h11 * s1;
        pT0 += h00 * t0 + h01 * t1;  pT1 += h10 * t0 + h11 * t1;
    }
    pS0 += __shfl_xor_sync(0xFFFFFFFFu, pS0, 1); pS0 += __shfl_xor_sync(0xFFFFFFFFu, pS0, 2);
    pS1 += __shfl_xor_sync(0xFFFFFFFFu, pS1, 1); pS1 += __shfl_xor_sync(0xFFFFFFFFu, pS1, 2);
    pT0 += __shfl_xor_sync(0xFFFFFFFFu, pT0, 1); pT0 += __shfl_xor_sync(0xFFFFFFFFu, pT0, 2);
    pT1 += __shfl_xor_sync(0xFFFFFFFFu, pT1, 1); pT1 += __shfl_xor_sync(0xFFFFFFFFu, pT1, 2);
    if (t == 0) {
        int b0i = node0 / NN, n0 = node0 - b0i * NN;
        atomicAdd(&g_asrc[n0 * 4 + b0i], pS0);
        atomicAdd(&g_atgt[n0 * 4 + b0i], pT0);
        int b1i = node1 / NN, n1 = node1 - b1i * NN;
        atomicAdd(&g_asrc[n1 * 4 + b1i], pS1);
        atomicAdd(&g_atgt[n1 * 4 + b1i], pT1);
    }
}

// ---------------- K3: edge weights ----------------
__global__ void __launch_bounds__(256) edgew_kernel(
    const int* __restrict__ edges, const float* __restrict__ ba) {
    int base = (blockIdx.x * blockDim.x + threadIdx.x) * 2;
    float partial = 0.0f;
    float ba0 = ba[0];
    if (base < EE) {
        int4 e4 = *(const int4*)(edges + 2 * base);
        float4 as0 = *(const float4*)(g_asrc + e4.x * 4);
        float4 at0 = *(const float4*)(g_atgt + e4.y * 4);
        float4 as1 = *(const float4*)(g_asrc + e4.z * 4);
        float4 at1 = *(const float4*)(g_atgt + e4.w * 4);
        float z0[4] = {as0.x + at0.x, as0.y + at0.y, as0.z + at0.z, as0.w + at0.w};
        float z1[4] = {as1.x + at1.x, as1.y + at1.y, as1.z + at1.z, as1.w + at1.w};
        float4 w0, w1;
        float* wp0 = (float*)&w0;
        float* wp1 = (float*)&w1;
#pragma unroll
        for (int b = 0; b < 4; b++) {
            float a0 = 1.0f - __fdividef(2.0f, __expf(2.0f * (z0[b] + ba0)) + 1.0f);
            float a1 = 1.0f - __fdividef(2.0f, __expf(2.0f * (z1[b] + ba0)) + 1.0f);
            float e0 = exp_poly(a0), e1 = exp_poly(a1);
            wp0[b] = e0; wp1[b] = e1;
            partial += e0 + e1;
        }
        g_w4[base] = w0;
        g_w4[base + 1] = w1;
    }
#pragma unroll
    for (int o = 16; o > 0; o >>= 1)
        partial += __shfl_xor_sync(0xFFFFFFFFu, partial, o);
    if ((threadIdx.x & 31) == 0) atomicAdd(g_expsum, partial);
}

// ---------------- K4: aggregate ----------------
__global__ void __launch_bounds__(256) agg_kernel() {
    int n = blockIdx.x * 8 + (threadIdx.x >> 5);
    int lane = threadIdx.x & 31;
    if (n >= NN) return;
    int cnt = g_cursor[n];
    if (cnt > CAP) cnt = CAP;
    float invS = 1.0f / g_expsum[0];
    const float4* hb = (const float4*)g_h;
    const unsigned int* bucket = g_csr + n * CAP;
    float4 a0 = make_float4(0.f, 0.f, 0.f, 0.f), a1 = a0, a2 = a0, a3 = a0;
    for (int j = 0; j < cnt; j++) {
        unsigned int v = bucket[j];
        int e = (int)(v >> 14);
        int tgt = (int)(v & 0x3FFFu);
        float4 w = g_w4[e];
        float4 h0 = hb[(size_t)(0 * NN + tgt) * 32 + lane];
        float4 h1 = hb[(size_t)(1 * NN + tgt) * 32 + lane];
        float4 h2 = hb[(size_t)(2 * NN + tgt) * 32 + lane];
        float4 h3 = hb[(size_t)(3 * NN + tgt) * 32 + lane];
        a0.x += w.x * h0.x; a0.y += w.x * h0.y; a0.z += w.x * h0.z; a0.w += w.x * h0.w;
        a1.x += w.y * h1.x; a1.y += w.y * h1.y; a1.z += w.y * h1.z; a1.w += w.y * h1.w;
        a2.x += w.z * h2.x; a2.y += w.z * h2.y; a2.z += w.z * h2.z; a2.w += w.z * h2.w;
        a3.x += w.w * h3.x; a3.y += w.w * h3.y; a3.z += w.w * h3.z; a3.w += w.w * h3.w;
    }
    a0.x *= invS; a0.y *= invS; a0.z *= invS; a0.w *= invS;
    a1.x *= invS; a1.y *= invS; a1.z *= invS; a1.w *= invS;
    a2.x *= invS; a2.y *= invS; a2.z *= invS; a2.w *= invS;
    a3.x *= invS; a3.y *= invS; a3.z *= invS; a3.w *= invS;
    float4* sc = (float4*)g_scat;
    sc[(size_t)(0 * NN + n) * 32 + lane] = a0;
    sc[(size_t)(1 * NN + n) * 32 + lane] = a1;
    sc[(size_t)(2 * NN + n) * 32 + lane] = a2;
    sc[(size_t)(3 * NN + n) * 32 + lane] = a3;
}

// ======================= output GEMM (2 x K=128 chunks) =======================
#define O_BH   0
#define O_BL   34816
#define O_AH   69632
#define O_AL   87040
#define O_BIAS 104448
#define O_SMEM 104960

__global__ void __launch_bounds__(256, 2) out_mma(
    const float* __restrict__ bc, float* __restrict__ out) {
    extern __shared__ char sm[];
    uint32_t sb = smem_u32(sm);
    float* bias = (float*)(sm + O_BIAS);

    const int tid = threadIdx.x, lane = tid & 31, w = tid >> 5;
    const int nb = blockIdx.x * 64;
    const int mg = w >> 1, nh = w & 1;
    const int nbase = nh * 64;

    if (tid < 128) bias[tid] = bc[tid];

    float D[8][4];
#pragma unroll
    for (int nt = 0; nt < 8; nt++)
#pragma unroll
        for (int j = 0; j < 4; j++) D[nt][j] = 0.0f;

#pragma unroll
    for (int c = 0; c < 2; c++) {
        if (c) __syncthreads();   // all warps done reading chunk-0 smem
        {
            uint4* dH = (uint4*)(sm + O_BH);
            uint4* dL = (uint4*)(sm + O_BL);
            const uint4* sH = g_OBH[c];
            const uint4* sL = g_OBL[c];
            for (int i = tid; i < 2176; i += 256) { dH[i] = sH[i]; dL[i] = sL[i]; }
        }
        stage_A64(c ? g_scat : g_h, nb,
                  (uint32_t*)(sm + O_AH), (uint32_t*)(sm + O_AL), tid);
        __syncthreads();
        mma_mainloop(sb + O_AH, sb + O_AL, sb + O_BH, sb + O_BL,
                     lane, mg, nbase, D);
    }

    const int g = lane >> 2, t = lane & 3;
    const int node0 = nb + mg * 16 + g;
    const int node1 = node0 + 8;
#pragma unroll
    for (int nt = 0; nt < 8; nt++) {
        int c = nbase + nt * 8 + 2 * t;
        float b0 = bias[c], b1 = bias[c + 1];
        float h00 = fmaxf(D[nt][0] + b0, 0.f), h01 = fmaxf(D[nt][1] + b1, 0.f);
        float h10 = fmaxf(D[nt][2] + b0, 0.f), h11 = fmaxf(D[nt][3] + b1, 0.f);
        *(float2*)(out + (size_t)node0 * 128 + c) = make_float2(h00, h01);
        *(float2*)(out + (size_t)node1 * 128 + c) = make_float2(h10, h11);
    }
}

// ---------------- launch ----------------
extern "C" void kernel_launch(void* const* d_in, const int* in_sizes, int n_in,
                              void* d_out, int out_size) {
    const float* nf    = (const float*)d_in[0];
    const int*   edges = (const int*)d_in[1];   // int32 (jax x64 disabled)
    const float* Wt    = (const float*)d_in[2];
    const float* bt    = (const float*)d_in[3];
    const float* Wa    = (const float*)d_in[4];
    const float* ba    = (const float*)d_in[5];
    const float* Wc    = (const float*)d_in[6];
    const float* bc    = (const float*)d_in[7];
    float*       out   = (float*)d_out;

    cudaFuncSetAttribute(transform_mma,
                         cudaFuncAttributeMaxDynamicSharedMemorySize, T_SMEM);
    cudaFuncSetAttribute(out_mma,
                         cudaFuncAttributeMaxDynamicSharedMemorySize, O_SMEM);

    zero_kernel<<<(NN * 4 + 255) / 256, 256>>>();
    prep_kernel<<<192, 256>>>(Wt, Wc);
    fill_kernel<<<(EE + 255) / 256, 256>>>(edges);
    transform_mma<<<BN / 64, 256, T_SMEM>>>(nf, bt, Wa);
    edgew_kernel<<<(EE / 2 + 255) / 256, 256>>>(edges, ba);
    agg_kernel<<<(NN + 7) / 8, 256>>>();
    out_mma<<<BN / 64, 256, O_SMEM>>>(bc, out);
}

// round 14
// speedup vs baseline: 1.9057x; 1.0443x over previous
#include <cuda_runtime.h>
#include <cuda_bf16.h>
#include <cstdint>

// Problem constants
#define BB   4
#define NN   10000
#define EE   160000
#define BN   40000
#define CAP  96

// ---------------- device scratch ----------------
__device__ float  g_h[BN * 128];
__device__ float  g_scat[BN * 128];
__device__ float  g_asrc[NN * 4];
__device__ float  g_atgt[NN * 4];
__device__ float4 g_w4[EE];
__device__ float  g_expsum[1];
__device__ int    g_cursor[NN];
__device__ unsigned int g_csr[NN * CAP];
// Precomputed bf16 hi/lo weight images, pitched [n=128][k=128], pitch 136 elems
__device__ uint4 g_TBH[2176], g_TBL[2176];        // Wt^T
__device__ uint4 g_OBH[2][2176], g_OBL[2][2176];  // Wc^T, two K=128 chunks

#define TPA 68          // A row pitch in u32 words (136 bf16)
#define TPB 136         // B row pitch in bf16 elems

// ---------------- helpers ----------------
__device__ __forceinline__ uint32_t smem_u32(const void* p) {
    uint32_t a;
    asm("{ .reg .u64 t; cvta.to.shared.u64 t, %1; cvt.u32.u64 %0, t; }"
        : "=r"(a) : "l"(p));
    return a;
}
__device__ __forceinline__ void mma16816(float* d, const uint32_t* a,
                                         const uint32_t* b) {
    asm volatile(
        "mma.sync.aligned.m16n8k16.row.col.f32.bf16.bf16.f32 "
        "{%0,%1,%2,%3}, {%4,%5,%6,%7}, {%8,%9}, {%0,%1,%2,%3};"
        : "+f"(d[0]), "+f"(d[1]), "+f"(d[2]), "+f"(d[3])
        : "r"(a[0]), "r"(a[1]), "r"(a[2]), "r"(a[3]), "r"(b[0]), "r"(b[1]));
}
__device__ __forceinline__ void ldsm_x4(uint32_t addr, uint32_t* r) {
    asm volatile(
        "ldmatrix.sync.aligned.m8n8.x4.shared.b16 {%0,%1,%2,%3}, [%4];"
        : "=r"(r[0]), "=r"(r[1]), "=r"(r[2]), "=r"(r[3]) : "r"(addr));
}
__device__ __forceinline__ void split_bf16(float v, uint16_t& h, uint16_t& l) {
    __nv_bfloat16 hb = __float2bfloat16(v);
    __nv_bfloat16 lb = __float2bfloat16(v - __bfloat162float(hb));
    h = *(uint16_t*)&hb;
    l = *(uint16_t*)&lb;
}
__device__ __forceinline__ void split_pack2(float x, float y, uint32_t& hi,
                                            uint32_t& lo) {
    uint16_t hx, lx, hy, ly;
    split_bf16(x, hx, lx);
    split_bf16(y, hy, ly);
    hi = (uint32_t)hx | ((uint32_t)hy << 16);
    lo = (uint32_t)lx | ((uint32_t)ly << 16);
}
__device__ __forceinline__ float exp_poly(float x) {
    float p = 1.98412698e-4f;
    p = fmaf(p, x, 1.38888889e-3f);
    p = fmaf(p, x, 8.33333333e-3f);
    p = fmaf(p, x, 4.16666667e-2f);
    p = fmaf(p, x, 1.66666667e-1f);
    p = fmaf(p, x, 0.5f);
    p = fmaf(p, x, 1.0f);
    p = fmaf(p, x, 1.0f);
    return p;
}

// K=128 bf16-split MMA mainloop via ldmatrix.x4. Warp: 16 rows x 32 cols.
// D[4][4]: nt = 2*p + half, cols nbase + nt*8.
__device__ __forceinline__ void mma_mainloop(
    uint32_t aH, uint32_t aL, uint32_t bH, uint32_t bL,
    int lane, int mg, int nbase, float D[4][4]) {
    const int m = lane >> 3, r8 = lane & 7;
    uint32_t aoff = (uint32_t)((mg * 16 + r8 + ((m & 1) << 3)) * (TPA * 4) +
                               ((m >> 1) << 4));
    uint32_t aHa = aH + aoff, aLa = aL + aoff;
    uint32_t bHa[2], bLa[2];
#pragma unroll
    for (int p = 0; p < 2; p++) {
        uint32_t boff = (uint32_t)((nbase + p * 16 + r8 + ((m >> 1) << 3)) *
                                   (TPB * 2) + ((m & 1) << 4));
        bHa[p] = bH + boff;
        bLa[p] = bL + boff;
    }
#pragma unroll
    for (int ks = 0; ks < 8; ks++) {
        uint32_t ah[4], al[4];
        ldsm_x4(aHa + ks * 32, ah);
        ldsm_x4(aLa + ks * 32, al);
        uint32_t bh[2][4], bl[2][4];
#pragma unroll
        for (int p = 0; p < 2; p++) {
            ldsm_x4(bHa[p] + ks * 32, bh[p]);
            ldsm_x4(bLa[p] + ks * 32, bl[p]);
        }
#pragma unroll
        for (int p = 0; p < 2; p++) {
            mma16816(D[2 * p],     ah, &bh[p][0]);
            mma16816(D[2 * p],     ah, &bl[p][0]);
            mma16816(D[2 * p],     al, &bh[p][0]);
            mma16816(D[2 * p + 1], ah, &bh[p][2]);
            mma16816(D[2 * p + 1], ah, &bl[p][2]);
            mma16816(D[2 * p + 1], al, &bh[p][2]);
        }
    }
}

// stage 64 node rows (128 floats each) as bf16 hi/lo into pitched A buffers
__device__ __forceinline__ void stage_A64(const float* __restrict__ src, int nb,
                                          uint32_t* AH, uint32_t* AL, int tid,
                                          int nthreads) {
    for (int i = tid; i < 2048; i += nthreads) {
        int node = i >> 5, c4 = i & 31;
        float4 v = *(const float4*)(src + (size_t)(nb + node) * 128 + c4 * 4);
        uint32_t h01, l01, h23, l23;
        split_pack2(v.x, v.y, h01, l01);
        split_pack2(v.z, v.w, h23, l23);
        int widx = node * TPA + c4 * 2;
        AH[widx] = h01; AH[widx + 1] = h23;
        AL[widx] = l01; AL[widx + 1] = l23;
    }
}

// ---------------- prep: weight images + zero init (fused) ----------------
__global__ void prep_kernel(const float* __restrict__ Wt,
                            const float* __restrict__ Wc) {
    int idx = blockIdx.x * blockDim.x + threadIdx.x;
    if (idx == 0) g_expsum[0] = 0.0f;
    if (idx < NN) g_cursor[idx] = 0;
    if (idx < NN * 4) { g_asrc[idx] = 0.0f; g_atgt[idx] = 0.0f; }
    if (idx < 16384) {
        int k = idx >> 7, n = idx & 127;
        uint16_t h, l;
        split_bf16(Wt[idx], h, l);
        ((uint16_t*)g_TBH)[n * TPB + k] = h;
        ((uint16_t*)g_TBL)[n * TPB + k] = l;
    } else if (idx < 49152) {
        int t = idx - 16384;
        int k = t >> 7, n = t & 127;
        int c = k >> 7, kk = k & 127;
        uint16_t h, l;
        split_bf16(Wc[t], h, l);
        ((uint16_t*)g_OBH[c])[n * TPB + kk] = h;
        ((uint16_t*)g_OBL[c])[n * TPB + kk] = l;
    }
}

// ---------------- K1: fill bucketed CSR ----------------
__global__ void fill_kernel(const int* __restrict__ edges) {
    int e = blockIdx.x * blockDim.x + threadIdx.x;
    if (e < EE) {
        int2 st = *(const int2*)(edges + 2 * e);
        int p = atomicAdd(&g_cursor[st.x], 1);
        if (p < CAP)
            g_csr[st.x * CAP + p] = ((unsigned int)e << 14) | (unsigned int)st.y;
    }
}

// ======================= transform GEMM =======================
// 512 threads = 16 warps = 4 M-groups x 4 N-quarters; 64 nodes/block.
#define T_BH   0
#define T_BL   34816
#define T_AH   69632
#define T_AL   87040
#define T_BIAS 104448
#define T_WAS  104960
#define T_WAT  105472
#define T_SMEM 105984

__global__ void __launch_bounds__(512, 2) transform_mma(
    const float* __restrict__ nf, const float* __restrict__ bt,
    const float* __restrict__ Wa) {
    extern __shared__ char sm[];
    uint32_t sb = smem_u32(sm);
    float* bias = (float*)(sm + T_BIAS);
    float* waS  = (float*)(sm + T_WAS);
    float* waT  = (float*)(sm + T_WAT);

    const int tid = threadIdx.x, lane = tid & 31, w = tid >> 5;
    const int nb = blockIdx.x * 64;

    {
        uint4* dH = (uint4*)(sm + T_BH);
        uint4* dL = (uint4*)(sm + T_BL);
        for (int i = tid; i < 2176; i += 512) { dH[i] = g_TBH[i]; dL[i] = g_TBL[i]; }
    }
    stage_A64(nf, nb, (uint32_t*)(sm + T_AH), (uint32_t*)(sm + T_AL), tid, 512);
    if (tid < 128) { bias[tid] = bt[tid]; waS[tid] = Wa[tid]; waT[tid] = Wa[128 + tid]; }
    __syncthreads();

    const int mg = w >> 2, nq = w & 3;
    const int nbase = nq * 32;

    float D[4][4];
#pragma unroll
    for (int nt = 0; nt < 4; nt++)
#pragma unroll
        for (int j = 0; j < 4; j++) D[nt][j] = 0.0f;

    mma_mainloop(sb + T_AH, sb + T_AL, sb + T_BH, sb + T_BL, lane, mg, nbase, D);

    // epilogue: relu + bias, store h, partial attention dots over 32 cols
    const int g = lane >> 2, t = lane & 3;
    const int node0 = nb + mg * 16 + g;
    const int node1 = node0 + 8;
    float pS0 = 0.f, pS1 = 0.f, pT0 = 0.f, pT1 = 0.f;
#pragma unroll
    for (int nt = 0; nt < 4; nt++) {
        int c = nbase + nt * 8 + 2 * t;
        float b0 = bias[c], b1 = bias[c + 1];
        float h00 = fmaxf(D[nt][0] + b0, 0.f), h01 = fmaxf(D[nt][1] + b1, 0.f);
        float h10 = fmaxf(D[nt][2] + b0, 0.f), h11 = fmaxf(D[nt][3] + b1, 0.f);
        *(float2*)(g_h + (size_t)node0 * 128 + c) = make_float2(h00, h01);
        *(float2*)(g_h + (size_t)node1 * 128 + c) = make_float2(h10, h11);
        float s0 = waS[c], s1 = waS[c + 1], t0 = waT[c], t1 = waT[c + 1];
        pS0 += h00 * s0 + h01 * s1;  pS1 += h10 * s0 + h11 * s1;
        pT0 += h00 * t0 + h01 * t1;  pT1 += h10 * t0 + h11 * t1;
    }
    pS0 += __shfl_xor_sync(0xFFFFFFFFu, pS0, 1); pS0 += __shfl_xor_sync(0xFFFFFFFFu, pS0, 2);
    pS1 += __shfl_xor_sync(0xFFFFFFFFu, pS1, 1); pS1 += __shfl_xor_sync(0xFFFFFFFFu, pS1, 2);
    pT0 += __shfl_xor_sync(0xFFFFFFFFu, pT0, 1); pT0 += __shfl_xor_sync(0xFFFFFFFFu, pT0, 2);
    pT1 += __shfl_xor_sync(0xFFFFFFFFu, pT1, 1); pT1 += __shfl_xor_sync(0xFFFFFFFFu, pT1, 2);
    if (t == 0) {
        int b0i = node0 / NN, n0 = node0 - b0i * NN;
        atomicAdd(&g_asrc[n0 * 4 + b0i], pS0);
        atomicAdd(&g_atgt[n0 * 4 + b0i], pT0);
        int b1i = node1 / NN, n1 = node1 - b1i * NN;
        atomicAdd(&g_asrc[n1 * 4 + b1i], pS1);
        atomicAdd(&g_atgt[n1 * 4 + b1i], pT1);
    }
}

// ---------------- K3: edge weights ----------------
__global__ void __launch_bounds__(256) edgew_kernel(
    const int* __restrict__ edges, const float* __restrict__ ba) {
    int base = (blockIdx.x * blockDim.x + threadIdx.x) * 2;
    float partial = 0.0f;
    float ba0 = ba[0];
    if (base < EE) {
        int4 e4 = *(const int4*)(edges + 2 * base);
        float4 as0 = *(const float4*)(g_asrc + e4.x * 4);
        float4 at0 = *(const float4*)(g_atgt + e4.y * 4);
        float4 as1 = *(const float4*)(g_asrc + e4.z * 4);
        float4 at1 = *(const float4*)(g_atgt + e4.w * 4);
        float z0[4] = {as0.x + at0.x, as0.y + at0.y, as0.z + at0.z, as0.w + at0.w};
        float z1[4] = {as1.x + at1.x, as1.y + at1.y, as1.z + at1.z, as1.w + at1.w};
        float4 w0, w1;
        float* wp0 = (float*)&w0;
        float* wp1 = (float*)&w1;
#pragma unroll
        for (int b = 0; b < 4; b++) {
            float a0 = 1.0f - __fdividef(2.0f, __expf(2.0f * (z0[b] + ba0)) + 1.0f);
            float a1 = 1.0f - __fdividef(2.0f, __expf(2.0f * (z1[b] + ba0)) + 1.0f);
            float e0 = exp_poly(a0), e1 = exp_poly(a1);
            wp0[b] = e0; wp1[b] = e1;
            partial += e0 + e1;
        }
        g_w4[base] = w0;
        g_w4[base + 1] = w1;
    }
#pragma unroll
    for (int o = 16; o > 0; o >>= 1)
        partial += __shfl_xor_sync(0xFFFFFFFFu, partial, o);
    if ((threadIdx.x & 31) == 0) atomicAdd(g_expsum, partial);
}

// ---------------- K4: aggregate ----------------
__global__ void __launch_bounds__(256) agg_kernel() {
    int n = blockIdx.x * 8 + (threadIdx.x >> 5);
    int lane = threadIdx.x & 31;
    if (n >= NN) return;
    int cnt = g_cursor[n];
    if (cnt > CAP) cnt = CAP;
    float invS = 1.0f / g_expsum[0];
    const float4* hb = (const float4*)g_h;
    const unsigned int* bucket = g_csr + n * CAP;
    float4 a0 = make_float4(0.f, 0.f, 0.f, 0.f), a1 = a0, a2 = a0, a3 = a0;
    for (int j = 0; j < cnt; j++) {
        unsigned int v = bucket[j];
        int e = (int)(v >> 14);
        int tgt = (int)(v & 0x3FFFu);
        float4 w = g_w4[e];
        float4 h0 = hb[(size_t)(0 * NN + tgt) * 32 + lane];
        float4 h1 = hb[(size_t)(1 * NN + tgt) * 32 + lane];
        float4 h2 = hb[(size_t)(2 * NN + tgt) * 32 + lane];
        float4 h3 = hb[(size_t)(3 * NN + tgt) * 32 + lane];
        a0.x += w.x * h0.x; a0.y += w.x * h0.y; a0.z += w.x * h0.z; a0.w += w.x * h0.w;
        a1.x += w.y * h1.x; a1.y += w.y * h1.y; a1.z += w.y * h1.z; a1.w += w.y * h1.w;
        a2.x += w.z * h2.x; a2.y += w.z * h2.y; a2.z += w.z * h2.z; a2.w += w.z * h2.w;
        a3.x += w.w * h3.x; a3.y += w.w * h3.y; a3.z += w.w * h3.z; a3.w += w.w * h3.w;
    }
    a0.x *= invS; a0.y *= invS; a0.z *= invS; a0.w *= invS;
    a1.x *= invS; a1.y *= invS; a1.z *= invS; a1.w *= invS;
    a2.x *= invS; a2.y *= invS; a2.z *= invS; a2.w *= invS;
    a3.x *= invS; a3.y *= invS; a3.z *= invS; a3.w *= invS;
    float4* sc = (float4*)g_scat;
    sc[(size_t)(0 * NN + n) * 32 + lane] = a0;
    sc[(size_t)(1 * NN + n) * 32 + lane] = a1;
    sc[(size_t)(2 * NN + n) * 32 + lane] = a2;
    sc[(size_t)(3 * NN + n) * 32 + lane] = a3;
}

// ======================= output GEMM (2 x K=128 chunks) =======================
#define O_BH   0
#define O_BL   34816
#define O_AH   69632
#define O_AL   87040
#define O_BIAS 104448
#define O_SMEM 104960

__global__ void __launch_bounds__(512, 2) out_mma(
    const float* __restrict__ bc, float* __restrict__ out) {
    extern __shared__ char sm[];
    uint32_t sb = smem_u32(sm);
    float* bias = (float*)(sm + O_BIAS);

    const int tid = threadIdx.x, lane = tid & 31, w = tid >> 5;
    const int nb = blockIdx.x * 64;
    const int mg = w >> 2, nq = w & 3;
    const int nbase = nq * 32;

    if (tid < 128) bias[tid] = bc[tid];

    float D[4][4];
#pragma unroll
    for (int nt = 0; nt < 4; nt++)
#pragma unroll
        for (int j = 0; j < 4; j++) D[nt][j] = 0.0f;

#pragma unroll
    for (int c = 0; c < 2; c++) {
        if (c) __syncthreads();
        {
            uint4* dH = (uint4*)(sm + O_BH);
            uint4* dL = (uint4*)(sm + O_BL);
            const uint4* sH = g_OBH[c];
            const uint4* sL = g_OBL[c];
            for (int i = tid; i < 2176; i += 512) { dH[i] = sH[i]; dL[i] = sL[i]; }
        }
        stage_A64(c ? g_scat : g_h, nb,
                  (uint32_t*)(sm + O_AH), (uint32_t*)(sm + O_AL), tid, 512);
        __syncthreads();
        mma_mainloop(sb + O_AH, sb + O_AL, sb + O_BH, sb + O_BL,
                     lane, mg, nbase, D);
    }

    const int g = lane >> 2, t = lane & 3;
    const int node0 = nb + mg * 16 + g;
    const int node1 = node0 + 8;
#pragma unroll
    for (int nt = 0; nt < 4; nt++) {
        int c = nbase + nt * 8 + 2 * t;
        float b0 = bias[c], b1 = bias[c + 1];
        float h00 = fmaxf(D[nt][0] + b0, 0.f), h01 = fmaxf(D[nt][1] + b1, 0.f);
        float h10 = fmaxf(D[nt][2] + b0, 0.f), h11 = fmaxf(D[nt][3] + b1, 0.f);
        *(float2*)(out + (size_t)node0 * 128 + c) = make_float2(h00, h01);
        *(float2*)(out + (size_t)node1 * 128 + c) = make_float2(h10, h11);
    }
}

// ---------------- launch ----------------
extern "C" void kernel_launch(void* const* d_in, const int* in_sizes, int n_in,
                              void* d_out, int out_size) {
    const float* nf    = (const float*)d_in[0];
    const int*   edges = (const int*)d_in[1];   // int32 (jax x64 disabled)
    const float* Wt    = (const float*)d_in[2];
    const float* bt    = (const float*)d_in[3];
    const float* Wa    = (const float*)d_in[4];
    const float* ba    = (const float*)d_in[5];
    const float* Wc    = (const float*)d_in[6];
    const float* bc    = (const float*)d_in[7];
    float*       out   = (float*)d_out;

    cudaFuncSetAttribute(transform_mma,
                         cudaFuncAttributeMaxDynamicSharedMemorySize, T_SMEM);
    cudaFuncSetAttribute(out_mma,
                         cudaFuncAttributeMaxDynamicSharedMemorySize, O_SMEM);

    prep_kernel<<<192, 256>>>(Wt, Wc);
    fill_kernel<<<(EE + 255) / 256, 256>>>(edges);
    transform_mma<<<BN / 64, 512, T_SMEM>>>(nf, bt, Wa);
    edgew_kernel<<<(EE / 2 + 255) / 256, 256>>>(edges, ba);
    agg_kernel<<<(NN + 7) / 8, 256>>>();
    out_mma<<<BN / 64, 512, O_SMEM>>>(bc, out);
}